// round 17
// baseline (speedup 1.0000x reference)
#include <cuda_runtime.h>
#include <cuda_fp16.h>
#include <cstdint>

#define SDIM 4096
#define DDIM 64
#define TM 128
#define TN 128
#define JSPLIT 4
#define ROWB (SDIM / TM)                     /* 32 */
#define TILES_PER_CTA (SDIM / (TN * JSPLIT)) /* 8 */
#define NCTA (ROWB * JSPLIT)                 /* 128 */
#define NTHREADS 256

// ---- smem: Q fp16 2x16K + double-buffered KV (KH,KM,VH,VL) 2x64K = 160KB ----
#define SM_Q   0
#define SM_KV0 32768
#define SM_KV1 98304
#define OFF_VH 32768                /* within a KV buffer */
#define OFF_VL 49152
#define SMEM_BYTES 163840
#define SM_RED SM_KV0               /* reused post-loop for reductions */

// Precomputed fp16 2-split images (smem-layout-exact, swizzle pre-applied)
__device__ char g_qimg[32][2][16384];    /* QH, QM */
__device__ char g_kvimg[32][4][16384];   /* KH, KM, VH, VL */
__device__ float g_outpart[JSPLIT][SDIM][DDIM];
__device__ float g_rpart[NCTA];
__device__ int g_arrive = 0;
__device__ int g_depart = 0;

// ---------------- PTX helpers (baseline sm_80/90 features only) ----------------
__device__ __forceinline__ uint32_t smem_u32(const void* p) {
    uint32_t a;
    asm("{ .reg .u64 t; cvta.to.shared.u64 t, %1; cvt.u32.u64 %0, t; }"
        : "=r"(a) : "l"(p));
    return a;
}
#define LDSM4(d0, d1, d2, d3, a) \
    asm volatile("ldmatrix.sync.aligned.m8n8.x4.shared.b16 {%0,%1,%2,%3}, [%4];" \
                 : "=r"(d0), "=r"(d1), "=r"(d2), "=r"(d3) : "r"(a))
#define LDSM4T(d0, d1, d2, d3, a) \
    asm volatile("ldmatrix.sync.aligned.m8n8.x4.trans.shared.b16 {%0,%1,%2,%3}, [%4];" \
                 : "=r"(d0), "=r"(d1), "=r"(d2), "=r"(d3) : "r"(a))
#define MMAF16(c, a, b0_, b1_) \
    asm volatile("mma.sync.aligned.m16n8k16.row.col.f32.f16.f16.f32 " \
                 "{%0,%1,%2,%3}, {%4,%5,%6,%7}, {%8,%9}, {%0,%1,%2,%3};" \
                 : "+f"((c)[0]), "+f"((c)[1]), "+f"((c)[2]), "+f"((c)[3]) \
                 : "r"((a)[0]), "r"((a)[1]), "r"((a)[2]), "r"((a)[3]), \
                   "r"(b0_), "r"(b1_))
#define CPASYNC16(dst, src) \
    asm volatile("cp.async.cg.shared.global [%0], [%1], 16;" :: "r"(dst), "l"(src))
#define CPASYNC_COMMIT() asm volatile("cp.async.commit_group;" ::: "memory")
#define CPASYNC_WAIT(n)  asm volatile("cp.async.wait_group %0;" :: "n"(n) : "memory")

// pack two f32 into f16x2 (lo in low half)
#define CVTPK_F16(r, lo, hi) \
    asm("cvt.rn.f16x2.f32 %0, %1, %2;" : "=r"(r) : "f"(hi), "f"(lo))

// fp16 2-split of a float pair: h = f16(x,y); l = f16(residual)
__device__ __forceinline__ void split2_pair_f16(float x, float y, uint32_t& h,
                                                uint32_t& l) {
    CVTPK_F16(h, x, y);
    __half2 hv = *reinterpret_cast<__half2*>(&h);
    float rx = x - __low2float(hv);
    float ry = y - __high2float(hv);
    CVTPK_F16(l, rx, ry);
}

// ------------------ precompute: split Q/K/V into smem-layout images ------------
__global__ void __launch_bounds__(512) precompute_split(
    const float* __restrict__ Q, const float* __restrict__ K,
    const float* __restrict__ V)
{
    const int m = blockIdx.x >> 5;       // 0=Q, 1=K, 2=V
    const int tile = blockIdx.x & 31;
    const int tid = threadIdx.x;
    const float* src = (m == 0) ? Q : (m == 1) ? K : V;
    char* base = (m == 0) ? &g_qimg[tile][0][0] : &g_kvimg[tile][(m == 1) ? 0 : 2][0];
#pragma unroll
    for (int p = 0; p < 4; ++p) {
        int c = tid + p * 512;           // float4 index 0..2047
        int row = c >> 4, q4 = (c & 15) * 4;
        float4 x = *(const float4*)(src + (size_t)(tile * 128 + row) * DDIM + q4);
        uint32_t b = (uint32_t)row * 128 + q4 * 2;
        uint32_t sw = b ^ ((b >> 3) & 0x70);
        uint32_t h01, l01, h23, l23;
        split2_pair_f16(x.x, x.y, h01, l01);
        split2_pair_f16(x.z, x.w, h23, l23);
        *(uint2*)(base + sw) = make_uint2(h01, h23);
        *(uint2*)(base + 16384 + sw) = make_uint2(l01, l23);
    }
}

// ------------------------------ main kernel ------------------------------
__global__ void __launch_bounds__(NTHREADS, 1) fused_attn_main(
    const float* __restrict__ U, const float* __restrict__ RR,
    float* __restrict__ out)
{
    extern __shared__ char smem[];
    const uint32_t sb = smem_u32(smem);
    const int tid = threadIdx.x;
    const int wid = tid >> 5;
    const int l = tid & 31;
    const int wr = wid >> 1;             // 0..3 : 32-row slice of i
    const int wc = wid & 1;              // 0..1 : 64-col slice of j (k-split)
    const int i0 = blockIdx.y * TM;
    const int jt0 = blockIdx.x * TILES_PER_CTA;
    const float CF = 8.0f / 0.9f;
    const float TRS = 0.03125f;          // 1/32 exact scale for TR split

    const uint32_t keysw = (uint32_t)(l & 7) << 4;
    const uint32_t rowA = (uint32_t)(l & 15) * 128;
    const uint32_t colA = (uint32_t)((l >> 4) << 4);
    const uint32_t rowB = (uint32_t)((l & 7) + 8 * (l >> 4)) * 128;
    const uint32_t colB = (uint32_t)(((l >> 3) & 1) << 4);

    // ---- prologue: Q (32KB) + KV tile0 (64KB) ----
    {
        const char* qsrc = &g_qimg[blockIdx.y][0][0];
#pragma unroll
        for (int p = 0; p < 8; ++p) {
            uint32_t off = (uint32_t)(tid + p * NTHREADS) * 16;
            CPASYNC16(sb + SM_Q + off, qsrc + off);
        }
        const char* kvsrc = &g_kvimg[jt0][0][0];
#pragma unroll
        for (int p = 0; p < 16; ++p) {
            uint32_t off = (uint32_t)(tid + p * NTHREADS) * 16;
            CPASYNC16(sb + SM_KV0 + off, kvsrc + off);
        }
        CPASYNC_COMMIT();
    }

    float rr0[2], rr1[2];
#pragma unroll
    for (int mt = 0; mt < 2; ++mt) {
        rr0[mt] = RR[i0 + 32 * wr + 16 * mt + (l >> 2)];
        rr1[mt] = RR[i0 + 32 * wr + 16 * mt + 8 + (l >> 2)];
    }

    float oacc[2][8][4];
#pragma unroll
    for (int mt = 0; mt < 2; ++mt)
#pragma unroll
        for (int dt = 0; dt < 8; ++dt)
#pragma unroll
            for (int e = 0; e < 4; ++e) oacc[mt][dt][e] = 0.0f;
    float rsum = 0.0f;

#pragma unroll 1
    for (int jt = 0; jt < TILES_PER_CTA; ++jt) {
        const int j0 = (jt0 + jt) * TN;
        const bool more = (jt + 1 < TILES_PER_CTA);
        const uint32_t kv = (jt & 1) ? SM_KV1 : SM_KV0;
        const uint32_t kvn = (jt & 1) ? SM_KV0 : SM_KV1;

        __syncthreads();  // all warps done reading buf[(jt+1)&1] from iter jt-1

        // -- stage KV(t+1) into the other buffer (lands during this tile) --
        if (more) {
            const char* kvsrc = &g_kvimg[jt0 + jt + 1][0][0];
#pragma unroll
            for (int p = 0; p < 16; ++p) {
                uint32_t off = (uint32_t)(tid + p * NTHREADS) * 16;
                CPASYNC16(sb + kvn + off, kvsrc + off);
            }
            CPASYNC_COMMIT();
        }
        if (more) { CPASYNC_WAIT(1); } else { CPASYNC_WAIT(0); }
        __syncthreads();  // buf[jt&1] (+Q on jt=0) visible CTA-wide

        // -- preload chunk 0's U (latency hidden under GEMM1) --
        const float* u0p[2];
        const float* u1p[2];
#pragma unroll
        for (int mt = 0; mt < 2; ++mt) {
            u0p[mt] = U + (size_t)(i0 + 32 * wr + 16 * mt + (l >> 2)) * SDIM +
                      j0 + 64 * wc + (l & 3) * 2;
            u1p[mt] = u0p[mt] + 8 * SDIM;
        }
        float2 cu0[2][2], cu1[2][2];
#pragma unroll
        for (int mt = 0; mt < 2; ++mt)
#pragma unroll
            for (int e2 = 0; e2 < 2; ++e2) {
                cu0[mt][e2] = *(const float2*)(u0p[mt] + 8 * e2);
                cu1[mt][e2] = *(const float2*)(u1p[mt] + 8 * e2);
            }

        // -- GEMM1 (fp16 2-split): S = hh + hm + mh; warp patch 32x64 --
        float sacc[2][8][4];
#pragma unroll
        for (int mt = 0; mt < 2; ++mt)
#pragma unroll
            for (int nt = 0; nt < 8; ++nt)
#pragma unroll
                for (int e = 0; e < 4; ++e) sacc[mt][nt][e] = 0.0f;

#pragma unroll
        for (int kt = 0; kt < 4; ++kt) {
            uint32_t am[2][2][4];   // [pa][mt]
#pragma unroll
            for (int pa = 0; pa < 2; ++pa)
#pragma unroll
                for (int mt = 0; mt < 2; ++mt) {
                    uint32_t addr = sb + SM_Q + (uint32_t)pa * 16384 +
                                    (uint32_t)(32 * wr + 16 * mt) * 128 +
                                    rowA + (((uint32_t)kt * 32 + colA) ^ keysw);
                    LDSM4(am[pa][mt][0], am[pa][mt][1], am[pa][mt][2],
                          am[pa][mt][3], addr);
                }
            // kept (pa,pb): pb=0 -> pa{0,1}; pb=1 -> pa{0}
#pragma unroll
            for (int pb = 0; pb < 2; ++pb) {
                uint32_t bm[8][2];
#pragma unroll
                for (int u = 0; u < 4; ++u) {
                    uint32_t addr = sb + kv + (uint32_t)pb * 16384 +
                                    (uint32_t)(64 * wc + 16 * u) * 128 +
                                    rowB + (((uint32_t)kt * 32 + colB) ^ keysw);
                    LDSM4(bm[2 * u][0], bm[2 * u][1], bm[2 * u + 1][0],
                          bm[2 * u + 1][1], addr);
                }
                const int npa = 2 - pb;
#pragma unroll
                for (int pa = 0; pa < 2; ++pa) {
                    if (pa >= npa) break;
#pragma unroll
                    for (int mt = 0; mt < 2; ++mt)
#pragma unroll
                        for (int nt = 0; nt < 8; ++nt)
                            MMAF16(sacc[mt][nt], am[pa][mt], bm[nt][0],
                                   bm[nt][1]);
                }
            }
        }

        // -- fused elementwise + GEMM2, chunked by kt2; U prefetched 1 ahead --
        {
#pragma unroll
            for (int kt2 = 0; kt2 < 4; ++kt2) {
                float2 nu0[2][2], nu1[2][2];
                if (kt2 < 3) {
#pragma unroll
                    for (int mt = 0; mt < 2; ++mt)
#pragma unroll
                        for (int e2 = 0; e2 < 2; ++e2) {
                            nu0[mt][e2] = *(const float2*)(u0p[mt] +
                                              16 * (kt2 + 1) + 8 * e2);
                            nu1[mt][e2] = *(const float2*)(u1p[mt] +
                                              16 * (kt2 + 1) + 8 * e2);
                        }
                }
                uint32_t bmh[8][2];
#pragma unroll
                for (int u = 0; u < 4; ++u) {
                    uint32_t addr = sb + kv + OFF_VH +
                                    (uint32_t)(64 * wc + 16 * kt2) * 128 +
                                    rowA + (((uint32_t)u * 32 + colA) ^ keysw);
                    LDSM4T(bmh[2 * u][0], bmh[2 * u][1], bmh[2 * u + 1][0],
                           bmh[2 * u + 1][1], addr);
                }
                uint32_t aH4[2][4], aL4[2][4];
#pragma unroll
                for (int mt = 0; mt < 2; ++mt) {
#pragma unroll
                    for (int e2 = 0; e2 < 2; ++e2) {
                        const int nt = 2 * kt2 + e2;
                        float t0 = (cu0[mt][e2].x >= 0.1f) ? sacc[mt][nt][0] * CF : 0.0f;
                        float t1 = (cu0[mt][e2].y >= 0.1f) ? sacc[mt][nt][1] * CF : 0.0f;
                        float t2 = (cu1[mt][e2].x >= 0.1f) ? sacc[mt][nt][2] * CF : 0.0f;
                        float t3 = (cu1[mt][e2].y >= 0.1f) ? sacc[mt][nt][3] * CF : 0.0f;
                        float r0 = floorf(t0 * rr0[mt]), r1 = floorf(t1 * rr0[mt]);
                        float r2 = floorf(t2 * rr1[mt]), r3 = floorf(t3 * rr1[mt]);
                        rsum += (r0 + r1) + (r2 + r3);
                        // TR scaled by 1/32 (exact) to stay in fp16 range
                        float tr0 = t0 * r0 * TRS, tr1 = t1 * r1 * TRS;
                        float tr2 = t2 * r2 * TRS, tr3 = t3 * r3 * TRS;
                        uint32_t h01, lo01, h23, lo23;
                        split2_pair_f16(tr0, tr1, h01, lo01);
                        split2_pair_f16(tr2, tr3, h23, lo23);
                        aH4[mt][e2 * 2] = h01; aH4[mt][e2 * 2 + 1] = h23;
                        aL4[mt][e2 * 2] = lo01; aL4[mt][e2 * 2 + 1] = lo23;
                    }
                }
#pragma unroll
                for (int mt = 0; mt < 2; ++mt)
#pragma unroll
                    for (int dt = 0; dt < 8; ++dt)
                        MMAF16(oacc[mt][dt], aH4[mt], bmh[dt][0], bmh[dt][1]);
                uint32_t bml[8][2];
#pragma unroll
                for (int u = 0; u < 4; ++u) {
                    uint32_t addr = sb + kv + OFF_VL +
                                    (uint32_t)(64 * wc + 16 * kt2) * 128 +
                                    rowA + (((uint32_t)u * 32 + colA) ^ keysw);
                    LDSM4T(bml[2 * u][0], bml[2 * u][1], bml[2 * u + 1][0],
                           bml[2 * u + 1][1], addr);
                }
#pragma unroll
                for (int mt = 0; mt < 2; ++mt)
#pragma unroll
                    for (int dt = 0; dt < 8; ++dt)
                        MMAF16(oacc[mt][dt], aL4[mt], bmh[dt][0], bmh[dt][1]);
#pragma unroll
                for (int mt = 0; mt < 2; ++mt)
#pragma unroll
                    for (int dt = 0; dt < 8; ++dt)
                        MMAF16(oacc[mt][dt], aH4[mt], bml[dt][0], bml[dt][1]);
                // rotate U ping-pong
#pragma unroll
                for (int mt = 0; mt < 2; ++mt)
#pragma unroll
                    for (int e2 = 0; e2 < 2; ++e2) {
                        cu0[mt][e2] = nu0[mt][e2];
                        cu1[mt][e2] = nu1[mt][e2];
                    }
            }
        }
    }

    // undo the 1/32 TR scale (exact)
#pragma unroll
    for (int mt = 0; mt < 2; ++mt)
#pragma unroll
        for (int dt = 0; dt < 8; ++dt)
#pragma unroll
            for (int e = 0; e < 4; ++e) oacc[mt][dt][e] *= 32.0f;

    // ---- cross-warp (wc) reduction of output partials via smem ----
    __syncthreads();
    float* rbuf = (float*)(smem + SM_RED);  // 4 wr x 2048 floats = 32KB
    if (wc == 1) {
#pragma unroll
        for (int mt = 0; mt < 2; ++mt)
#pragma unroll
            for (int dt = 0; dt < 8; ++dt)
#pragma unroll
                for (int e = 0; e < 4; ++e)
                    rbuf[wr * 2048 + ((mt * 8 + dt) * 4 + e) * 32 + l] =
                        oacc[mt][dt][e];
    }
    __syncthreads();
    if (wc == 0) {
#pragma unroll
        for (int mt = 0; mt < 2; ++mt)
#pragma unroll
            for (int dt = 0; dt < 8; ++dt) {
                float c0 = oacc[mt][dt][0] +
                           rbuf[wr * 2048 + ((mt * 8 + dt) * 4 + 0) * 32 + l];
                float c1 = oacc[mt][dt][1] +
                           rbuf[wr * 2048 + ((mt * 8 + dt) * 4 + 1) * 32 + l];
                float c2 = oacc[mt][dt][2] +
                           rbuf[wr * 2048 + ((mt * 8 + dt) * 4 + 2) * 32 + l];
                float c3 = oacc[mt][dt][3] +
                           rbuf[wr * 2048 + ((mt * 8 + dt) * 4 + 3) * 32 + l];
                int r0 = i0 + 32 * wr + 16 * mt + (l >> 2);
                int col = 8 * dt + (l & 3) * 2;
                *(float2*)(&g_outpart[blockIdx.x][r0][col]) = make_float2(c0, c1);
                *(float2*)(&g_outpart[blockIdx.x][r0 + 8][col]) = make_float2(c2, c3);
            }
    }

    // ---- deterministic rsum reduction ----
#pragma unroll
    for (int off = 16; off; off >>= 1)
        rsum += __shfl_xor_sync(0xffffffffu, rsum, off);
    float* red = (float*)(smem + SM_RED);
    __syncthreads();
    if (l == 0) red[wid] = rsum;
    __syncthreads();
    if (tid == 0) {
        float tot = 0.0f;
#pragma unroll
        for (int w = 0; w < 8; ++w) tot += red[w];
        g_rpart[blockIdx.y * JSPLIT + blockIdx.x] = tot;
    }

    // ---- device-wide barrier (128 CTAs all co-resident: 160KB smem => 1/SM) ----
    __threadfence();
    __syncthreads();
    if (tid == 0) atomicAdd(&g_arrive, 1);

    if (blockIdx.x == 0) {
        if (tid == 0) {
            while (atomicAdd(&g_arrive, 0) < NCTA) __nanosleep(64);
            __threadfence();
        }
        __syncthreads();
        float* red2 = (float*)smem;
        if (tid < NCTA) red2[tid] = __ldcg(&g_rpart[tid]);
        __syncthreads();
#pragma unroll
        for (int s = 64; s > 0; s >>= 1) {
            if (tid < s) red2[tid] += red2[tid + s];
            __syncthreads();
        }
        const float R = red2[0];
        const float* base = &g_outpart[0][0][0];
        const size_t part = (size_t)SDIM * DDIM;
        const size_t rowbase = (size_t)i0 * DDIM / 4;
#pragma unroll
        for (int p = 0; p < 8; ++p) {
            size_t idx = rowbase + (size_t)p * NTHREADS + tid;
            float4 a = __ldcg((const float4*)(base + idx * 4));
            float4 b = __ldcg((const float4*)(base + part + idx * 4));
            float4 c = __ldcg((const float4*)(base + 2 * part + idx * 4));
            float4 d = __ldcg((const float4*)(base + 3 * part + idx * 4));
            float4 o;
            o.x = (((a.x + b.x) + c.x) + d.x) / R;
            o.y = (((a.y + b.y) + c.y) + d.y) / R;
            o.z = (((a.z + b.z) + c.z) + d.z) / R;
            o.w = (((a.w + b.w) + c.w) + d.w) / R;
            *(float4*)(out + idx * 4) = o;
        }
    }

    __syncthreads();
    if (tid == 0) {
        int old = atomicAdd(&g_depart, 1);
        if (old == NCTA - 1) {
            atomicExch(&g_arrive, 0);
            atomicExch(&g_depart, 0);
            __threadfence();
        }
    }
}

extern "C" void kernel_launch(void* const* d_in, const int* in_sizes, int n_in,
                              void* d_out, int out_size)
{
    const float* Q  = (const float*)d_in[0];
    const float* K  = (const float*)d_in[1];
    const float* V  = (const float*)d_in[2];
    const float* U  = (const float*)d_in[3];
    const float* RR = (const float*)d_in[4];
    float* out = (float*)d_out;

    cudaFuncSetAttribute(fused_attn_main,
                         cudaFuncAttributeMaxDynamicSharedMemorySize, SMEM_BYTES);

    precompute_split<<<96, 512>>>(Q, K, V);
    dim3 grid(JSPLIT, ROWB);
    fused_attn_main<<<grid, NTHREADS, SMEM_BYTES>>>(U, RR, out);
}